// round 11
// baseline (speedup 1.0000x reference)
#include <cuda_runtime.h>
#include <cuda_bf16.h>
#include <math.h>
#include <stdint.h>

// Problem constants
#define BB   16
#define NN   512
#define CC   768
#define HH   12
#define DD   64
#define HID  3072
#define M_TOK (BB*NN)          // 8192

// ---------------- scratch (device globals; no allocations) ----------------
__device__ __nv_bfloat16 g_hb  [M_TOK * CC];
__device__ __nv_bfloat16 g_qkvb[M_TOK * 3*CC];
__device__ __nv_bfloat16 g_ob  [M_TOK * CC];
__device__ __nv_bfloat16 g_h2b [M_TOK * CC];
__device__ __nv_bfloat16 g_hidb[M_TOK * HID];
__device__ __nv_bfloat16 g_biasb[HH * NN * NN];  // rel-pos bias (x log2e)
__device__ float         g_part[3 * M_TOK * CC]; // fc2 split-K partials
// bf16 weights
__device__ __nv_bfloat16 g_wqkv [3*CC*CC];
__device__ __nv_bfloat16 g_wproj[CC*CC];
__device__ __nv_bfloat16 g_w1t  [HID*CC];
__device__ __nv_bfloat16 g_w1f  [HID*CC];
__device__ __nv_bfloat16 g_w2t  [CC*HID];
__device__ __nv_bfloat16 g_w2f  [CC*HID];

// ---------------- PTX helpers ----------------
__device__ __forceinline__ uint32_t smem_u32(const void* p) {
    uint32_t a;
    asm("{ .reg .u64 t; cvta.to.shared.u64 t, %1; cvt.u32.u64 %0, t; }" : "=r"(a) : "l"(p));
    return a;
}
__device__ __forceinline__ float ex2f(float x) {
    float r;
    asm("ex2.approx.ftz.f32 %0, %1;" : "=f"(r) : "f"(x));
    return r;
}
#define CP16(dst, src) \
    asm volatile("cp.async.cg.shared.global [%0], [%1], 16;" :: "r"(dst), "l"(src))
#define CPCOMMIT() asm volatile("cp.async.commit_group;" ::: "memory")
#define CPWAIT(n)  asm volatile("cp.async.wait_group %0;" :: "n"(n) : "memory")
#define LDSM4(r0, r1, r2, r3, addr) \
    asm volatile("ldmatrix.sync.aligned.m8n8.x4.shared.b16 {%0,%1,%2,%3}, [%4];" \
        : "=r"(r0), "=r"(r1), "=r"(r2), "=r"(r3) : "r"(addr))
#define LDSM4T(r0, r1, r2, r3, addr) \
    asm volatile("ldmatrix.sync.aligned.m8n8.x4.trans.shared.b16 {%0,%1,%2,%3}, [%4];" \
        : "=r"(r0), "=r"(r1), "=r"(r2), "=r"(r3) : "r"(addr))
#define MMA16816(c, a, b) \
    asm volatile("mma.sync.aligned.m16n8k16.row.col.f32.bf16.bf16.f32 " \
        "{%0,%1,%2,%3}, {%4,%5,%6,%7}, {%8,%9}, {%0,%1,%2,%3};" \
        : "+f"((c)[0]), "+f"((c)[1]), "+f"((c)[2]), "+f"((c)[3]) \
        : "r"((a)[0]), "r"((a)[1]), "r"((a)[2]), "r"((a)[3]), "r"((b)[0]), "r"((b)[1]))

#define SW128(row, ch) ((uint32_t)((row)*128 + ((((ch) ^ ((row)&7))) << 4)))

// ---------------- fp32 -> bf16 weight converts (two batches) ----------------
#define CA0 442368
#define CA1 (CA0 + 147456)
__global__ __launch_bounds__(256)
void cvt_a(const float4* __restrict__ s0, const float4* __restrict__ s1,
           __nv_bfloat162* __restrict__ d0, __nv_bfloat162* __restrict__ d1)
{
    int i = blockIdx.x * 256 + threadIdx.x;
    if (i >= CA1) return;
    const float4* s; __nv_bfloat162* d; int off;
    if (i < CA0) { s = s0; d = d0; off = i; }
    else         { s = s1; d = d1; off = i - CA0; }
    float4 v = s[off];
    d[2*off]   = __floats2bfloat162_rn(v.x, v.y);
    d[2*off+1] = __floats2bfloat162_rn(v.z, v.w);
}
#define CB0 589824
__global__ __launch_bounds__(256)
void cvt_b(const float4* __restrict__ s0, const float4* __restrict__ s1,
           const float4* __restrict__ s2, const float4* __restrict__ s3,
           __nv_bfloat162* __restrict__ d0, __nv_bfloat162* __restrict__ d1,
           __nv_bfloat162* __restrict__ d2, __nv_bfloat162* __restrict__ d3)
{
    int i = blockIdx.x * 256 + threadIdx.x;
    if (i >= 4*CB0) return;
    int seg = i / CB0, off = i - seg*CB0;
    const float4* s = (seg == 0) ? s0 : (seg == 1) ? s1 : (seg == 2) ? s2 : s3;
    __nv_bfloat162* d = (seg == 0) ? d0 : (seg == 1) ? d1 : (seg == 2) ? d2 : d3;
    float4 v = s[off];
    d[2*off]   = __floats2bfloat162_rn(v.x, v.y);
    d[2*off+1] = __floats2bfloat162_rn(v.z, v.w);
}

// ---------------- rel-pos bias precompute ----------------
__global__ __launch_bounds__(256)
void bias_kernel(const int* __restrict__ rpi, const float* __restrict__ table,
                 __nv_bfloat16* __restrict__ out)
{
    int e = blockIdx.x * 256 + threadIdx.x;
    int idx = rpi[e];
    const float* t = table + (size_t)idx * HH;
    #pragma unroll
    for (int h = 0; h < HH; ++h)
        out[(size_t)h * (NN*NN) + e] = __float2bfloat16(t[h] * 1.4426950408889634f);
}

// ---------------- LayerNorm: 2 rows per 384-thread CTA ----------------
__global__ __launch_bounds__(384)
void ln_kernel(const float4* __restrict__ x4, uint2* __restrict__ out,
               const float4* __restrict__ g0, const float4* __restrict__ b0,
               const float4* __restrict__ g1, const float4* __restrict__ b1,
               int split)
{
    int half = threadIdx.x >= 192;           // which row of the pair
    int m = blockIdx.x * 2 + half;
    int t = threadIdx.x - half * 192;        // 0..191 within row
    float4 v = x4[(size_t)m * 192 + t];
    float s  = (v.x + v.y) + (v.z + v.w);
    float sq = (v.x*v.x + v.y*v.y) + (v.z*v.z + v.w*v.w);

    __shared__ float r1[2][6], r2[2][6];
    #pragma unroll
    for (int o = 16; o; o >>= 1) {
        s  += __shfl_xor_sync(0xffffffffu, s,  o);
        sq += __shfl_xor_sync(0xffffffffu, sq, o);
    }
    int wir = t >> 5;                        // warp index within row (0..5)
    if ((t & 31) == 0) { r1[half][wir] = s; r2[half][wir] = sq; }
    __syncthreads();
    float tot = 0.f, totq = 0.f;
    #pragma unroll
    for (int i = 0; i < 6; i++) { tot += r1[half][i]; totq += r2[half][i]; }
    float mean = tot * (1.f / CC);
    float var  = totq * (1.f / CC) - mean * mean;
    float inv  = rsqrtf(var + 1e-5f);

    const float4* g = g0; const float4* bb = b0;
    if (split && (m & (NN - 1)) >= 256) { g = g1; bb = b1; }
    float4 gv = g[t], bv = bb[t];
    float o0 = (v.x - mean) * inv * gv.x + bv.x;
    float o1 = (v.y - mean) * inv * gv.y + bv.y;
    float o2 = (v.z - mean) * inv * gv.z + bv.z;
    float o3 = (v.w - mean) * inv * gv.w + bv.w;
    __nv_bfloat162 p0 = __floats2bfloat162_rn(o0, o1);
    __nv_bfloat162 p1 = __floats2bfloat162_rn(o2, o3);
    out[(size_t)m * 192 + t] = make_uint2(*(uint32_t*)&p0, *(uint32_t*)&p1);
}

// ---------------- HMMA bf16 GEMM, templated N-tile ----------------
// BM=128, BN in {128, 64}. 256 threads (8 warps: wm 0..3 x wn 0..1),
// warp tile 32 x (BN/2). BK=64, 3-stage pipeline (round-7 issue-before-wait).
template<int EPI, bool SPLIT, int BN>
__global__ __launch_bounds__(256, 2)
void mma_gemm(const __nv_bfloat16* __restrict__ A, int K, int ldk, int N,
              const __nv_bfloat16* __restrict__ W0, const __nv_bfloat16* __restrict__ W1,
              const float* __restrict__ bias0, const float* __restrict__ bias1,
              const float* __restrict__ res, const float* __restrict__ gamma,
              float* __restrict__ outf, __nv_bfloat16* __restrict__ outb)
{
    constexpr uint32_t BSTG = (uint32_t)BN * 128u;   // B bytes per stage
    constexpr uint32_t STG  = 16384u + BSTG;         // stage stride
    constexpr int JP = BN / 32;                      // B ldmatrix groups
    constexpr int JN = BN / 16;                      // n-frags per warp

    extern __shared__ char gsm[];
    const int m0 = blockIdx.y * 128;
    const int n0 = blockIdx.x * BN;
    const int koff = blockIdx.z * K;
    const __nv_bfloat16* W = W0;
    const float* bias = bias0;
    if (SPLIT && ((m0 & (NN - 1)) >= 256)) { W = W1; bias = bias1; }

    const int tid  = threadIdx.x;
    const int lane = tid & 31;
    const int wid  = tid >> 5;
    const int wm   = wid >> 1;   // 0..3
    const int wn   = wid & 1;    // 0..1

    const uint32_t asb = smem_u32(gsm);
    const uint32_t bsb = asb + 16384u;

    const int lrow = tid >> 3;
    const int lch  = tid & 7;

    float c[2][JN][4];
    #pragma unroll
    for (int i = 0; i < 2; i++)
        #pragma unroll
        for (int j = 0; j < JN; j++)
            #pragma unroll
            for (int q = 0; q < 4; q++) c[i][j][q] = 0.f;

    const int nk = K >> 6;

    auto issue = [&](int kc, int stg) {
        const __nv_bfloat16* Ap = A + koff + (size_t)m0 * ldk + kc*64;
        const __nv_bfloat16* Wp = W + koff + (size_t)n0 * ldk + kc*64;
        const uint32_t ao = asb + (uint32_t)stg * STG;
        const uint32_t bo = bsb + (uint32_t)stg * STG;
        #pragma unroll
        for (int it = 0; it < 4; ++it) {
            int row = it*32 + lrow;
            CP16(ao + SW128(row, lch), Ap + (size_t)row * ldk + lch*8);
        }
        #pragma unroll
        for (int it = 0; it < BN/32; ++it) {
            int row = it*32 + lrow;
            CP16(bo + SW128(row, lch), Wp + (size_t)row * ldk + lch*8);
        }
    };

    issue(0, 0); CPCOMMIT();
    if (nk > 1) issue(1, 1);
    CPCOMMIT();

    for (int kc = 0; kc < nk; ++kc) {
        if (kc + 2 < nk) issue(kc + 2, (kc + 2) % 3);
        CPCOMMIT();
        CPWAIT(2);
        __syncthreads();

        const uint32_t ab = asb + (uint32_t)(kc % 3) * STG;
        const uint32_t bb = bsb + (uint32_t)(kc % 3) * STG;
        #pragma unroll
        for (int kk = 0; kk < 4; ++kk) {
            uint32_t a[2][4];
            #pragma unroll
            for (int i = 0; i < 2; ++i) {
                int row = wm*32 + i*16 + (lane & 7) + ((lane >> 3) & 1) * 8;
                int ch  = 2*kk + (lane >> 4);
                LDSM4(a[i][0], a[i][1], a[i][2], a[i][3], ab + SW128(row, ch));
            }
            uint32_t b[JN][2];
            #pragma unroll
            for (int jp = 0; jp < JP; ++jp) {
                int row = wn*(BN/2) + jp*16 + (lane & 7) + (lane >> 4) * 8;
                int ch  = 2*kk + ((lane >> 3) & 1);
                uint32_t t0, t1, t2, t3;
                LDSM4(t0, t1, t2, t3, bb + SW128(row, ch));
                b[jp*2][0] = t0; b[jp*2][1] = t1;
                b[jp*2+1][0] = t2; b[jp*2+1][1] = t3;
            }
            #pragma unroll
            for (int i = 0; i < 2; ++i)
                #pragma unroll
                for (int j = 0; j < JN; ++j)
                    MMA16816(c[i][j], a[i], b[j]);
        }
        __syncthreads();
    }

    float* outz = (EPI == 0) ? (outf + (size_t)blockIdx.z * M_TOK * N) : outf;
    const int g  = lane >> 2;
    const int t4 = lane & 3;
    #pragma unroll
    for (int i = 0; i < 2; ++i) {
        #pragma unroll
        for (int half = 0; half < 2; ++half) {
            const int m = m0 + wm*32 + i*16 + g + half*8;
            #pragma unroll
            for (int j = 0; j < JN; ++j) {
                const int n = n0 + wn*(BN/2) + j*8 + t4*2;
                const float v0 = c[i][j][half*2+0];
                const float v1 = c[i][j][half*2+1];
                const size_t idx = (size_t)m * N + n;
                if (EPI == 0) {
                    *(float2*)(outz + idx) = make_float2(v0, v1);
                } else if (EPI == 1) {
                    float ga = __ldg(gamma + n), gb = __ldg(gamma + n + 1);
                    float ba = __ldg(bias + n),  bbv = __ldg(bias + n + 1);
                    float ra = __ldg(res + idx), rb = __ldg(res + idx + 1);
                    *(float2*)(outf + idx) = make_float2(ra + ga*(v0 + ba), rb + gb*(v1 + bbv));
                } else if (EPI == 2) {
                    float x0 = v0 + __ldg(bias + n);
                    float x1 = v1 + __ldg(bias + n + 1);
                    float e0 = 0.5f * x0 * (1.f + erff(x0 * 0.70710678118654752440f));
                    float e1 = 0.5f * x1 * (1.f + erff(x1 * 0.70710678118654752440f));
                    *(__nv_bfloat162*)(outb + idx) = __floats2bfloat162_rn(e0, e1);
                } else { // EPI == 4
                    *(__nv_bfloat162*)(outb + idx) = __floats2bfloat162_rn(v0, v1);
                }
            }
        }
    }
}

// ---------------- fc2 split-K=3 reduce ----------------
__global__ __launch_bounds__(256)
void fc2_reduce(const float* __restrict__ part, const float* __restrict__ bt,
                const float* __restrict__ bf, const float* __restrict__ gamma,
                float* __restrict__ out)
{
    int i = blockIdx.x * 256 + threadIdx.x;
    size_t idx = (size_t)i * 4;
    int m = (int)(idx / CC);
    int n = (int)(idx % CC);
    const float* bias = ((m & (NN - 1)) >= 256) ? bf : bt;
    float4 p0 = *(const float4*)(part + idx);
    float4 p1 = *(const float4*)(part + (size_t)M_TOK*CC + idx);
    float4 p2 = *(const float4*)(part + 2*(size_t)M_TOK*CC + idx);
    float4 o  = *(const float4*)(out + idx);
    float4 gm = *(const float4*)(gamma + n);
    float4 bs = *(const float4*)(bias + n);
    o.x += gm.x * (p0.x + p1.x + p2.x + bs.x);
    o.y += gm.y * (p0.y + p1.y + p2.y + bs.y);
    o.z += gm.z * (p0.z + p1.z + p2.z + bs.z);
    o.w += gm.w * (p0.w + p1.w + p2.w + bs.w);
    *(float4*)(out + idx) = o;
}

// ---------------- FlashAttention (no-max) ----------------
#define FA_Q   0u
#define FA_KV  8192u
#define FA_P   57344u
#define FA_L   73728u
#define FASMEM 74240
__global__ __launch_bounds__(256, 2)
void attn_fa(const __nv_bfloat16* __restrict__ qkvb, const __nv_bfloat16* __restrict__ biasb,
             __nv_bfloat16* __restrict__ ob)
{
    extern __shared__ char sm[];
    const uint32_t sb = smem_u32(sm);
    float* lh = (float*)(sm + FA_L);

    const int q0 = blockIdx.x * 64;
    const int h  = blockIdx.y;
    const int b  = blockIdx.z;
    const int tid = threadIdx.x;
    const int lane = tid & 31;
    const int wid  = tid >> 5;
    const int wm   = wid >> 1;
    const int wn   = wid & 1;
    const int lq   = lane >> 2;
    const int lt   = lane & 3;
    const int r0   = wm*16 + lq;

    const __nv_bfloat16* brow = biasb + (size_t)h * (NN*NN);
    const float LOG2E_SCALE = 0.125f * 1.4426950408889634f;

    auto issueT = [&](int tile, int co, int bufi) {
        uint32_t base = sb + FA_KV + (uint32_t)bufi * 16384u;
        #pragma unroll
        for (int it = 0; it < 4; ++it) {
            int e = it*256 + tid;
            int row = e >> 3, ch = e & 7;
            CP16(base + SW128(row, ch),
                 qkvb + (size_t)(b*NN + tile*128 + row) * (3*CC) + co + h*DD + ch*8);
        }
    };

    #pragma unroll
    for (int it = 0; it < 2; ++it) {
        int e = it*256 + tid;
        int row = e >> 3, ch = e & 7;
        CP16(sb + FA_Q + SW128(row, ch),
             qkvb + (size_t)(b*NN + q0 + row) * (3*CC) + h*DD + ch*8);
    }
    issueT(0, CC, 0);
    CPCOMMIT();
    issueT(0, 2*CC, 1);
    CPCOMMIT();

    float o[4][4];
    #pragma unroll
    for (int j = 0; j < 4; ++j)
        #pragma unroll
        for (int q = 0; q < 4; ++q) o[j][q] = 0.f;
    float l0r = 0.f, l1r = 0.f;

    for (int t = 0; t < 4; ++t) {
        CPWAIT(1);
        __syncthreads();
        if (t < 3) { issueT(t + 1, CC, (2*t + 2) % 3); CPCOMMIT(); }
        const uint32_t vbase = sb + FA_KV + (uint32_t)((2*t + 1) % 3) * 16384u;
        const uint32_t kbase = sb + FA_KV + (uint32_t)((2*t) % 3) * 16384u;

        float s[8][4];
        #pragma unroll
        for (int j = 0; j < 8; ++j)
            #pragma unroll
            for (int q = 0; q < 4; ++q) s[j][q] = 0.f;
        #pragma unroll
        for (int kk = 0; kk < 4; ++kk) {
            uint32_t a[4];
            {
                int row = wm*16 + (lane & 7) + ((lane >> 3) & 1) * 8;
                int ch  = 2*kk + (lane >> 4);
                LDSM4(a[0], a[1], a[2], a[3], sb + FA_Q + SW128(row, ch));
            }
            uint32_t bfr[8][2];
            #pragma unroll
            for (int jp = 0; jp < 4; ++jp) {
                int row = wn*64 + jp*16 + (lane & 7) + (lane >> 4) * 8;
                int ch  = 2*kk + ((lane >> 3) & 1);
                uint32_t t0, t1, t2, t3;
                LDSM4(t0, t1, t2, t3, kbase + SW128(row, ch));
                bfr[jp*2][0] = t0; bfr[jp*2][1] = t1;
                bfr[jp*2+1][0] = t2; bfr[jp*2+1][1] = t3;
            }
            #pragma unroll
            for (int j = 0; j < 8; ++j)
                MMA16816(s[j], a, bfr[j]);
        }

        float ts0 = 0.f, ts1 = 0.f;
        #pragma unroll
        for (int j = 0; j < 8; ++j) {
            int cg = t*128 + wn*64 + j*8 + lt*2;
            __nv_bfloat162 b0 = *(const __nv_bfloat162*)(brow + (size_t)(q0 + r0) * NN + cg);
            __nv_bfloat162 b1 = *(const __nv_bfloat162*)(brow + (size_t)(q0 + r0 + 8) * NN + cg);
            float p0 = ex2f(fmaf(s[j][0], LOG2E_SCALE, __bfloat162float(b0.x)));
            float p1 = ex2f(fmaf(s[j][1], LOG2E_SCALE, __bfloat162float(b0.y)));
            float p2 = ex2f(fmaf(s[j][2], LOG2E_SCALE, __bfloat162float(b1.x)));
            float p3 = ex2f(fmaf(s[j][3], LOG2E_SCALE, __bfloat162float(b1.y)));
            ts0 += p0 + p1;
            ts1 += p2 + p3;
            int chp = (wn*8 + j);
            __nv_bfloat162 q01 = __floats2bfloat162_rn(p0, p1);
            __nv_bfloat162 q23 = __floats2bfloat162_rn(p2, p3);
            *(uint32_t*)(sm + FA_P + (uint32_t)(r0*256)       + (uint32_t)((chp ^ lq) << 4) + (uint32_t)(lt*4)) = *(uint32_t*)&q01;
            *(uint32_t*)(sm + FA_P + (uint32_t)((r0 + 8)*256) + (uint32_t)((chp ^ lq) << 4) + (uint32_t)(lt*4)) = *(uint32_t*)&q23;
        }
        ts0 += __shfl_xor_sync(0xffffffffu, ts0, 1);
        ts0 += __shfl_xor_sync(0xffffffffu, ts0, 2);
        ts1 += __shfl_xor_sync(0xffffffffu, ts1, 1);
        ts1 += __shfl_xor_sync(0xffffffffu, ts1, 2);
        if (lt == 0) { lh[wn*64 + r0] = ts0; lh[wn*64 + r0 + 8] = ts1; }
        __syncthreads();
        l0r += lh[r0]     + lh[64 + r0];
        l1r += lh[r0 + 8] + lh[64 + r0 + 8];

        if (t < 3) { CPWAIT(1); } else { CPWAIT(0); }
        #pragma unroll
        for (int kk = 0; kk < 8; ++kk) {
            uint32_t a[4];
            {
                int row = wm*16 + (lane & 7) + ((lane >> 3) & 1) * 8;
                int chp = kk*2 + (lane >> 4);
                LDSM4(a[0], a[1], a[2], a[3],
                      sb + FA_P + (uint32_t)(row*256) + (uint32_t)(((chp ^ (row & 7))) << 4));
            }
            #pragma unroll
            for (int half = 0; half < 2; ++half) {
                int krow = kk*16 + (lane & 7) + ((lane >> 3) & 1) * 8;
                int ch   = wn*4 + half*2 + (lane >> 4);
                uint32_t t0, t1, t2, t3;
                LDSM4T(t0, t1, t2, t3, vbase + SW128(krow, ch));
                uint32_t bv0[2] = {t0, t1}, bv1[2] = {t2, t3};
                MMA16816(o[half*2],     a, bv0);
                MMA16816(o[half*2 + 1], a, bv1);
            }
        }
        if (t < 3) { issueT(t + 1, 2*CC, (2*t + 3) % 3); CPCOMMIT(); }
    }

    float i0 = 1.f / l0r, i1 = 1.f / l1r;
    #pragma unroll
    for (int j = 0; j < 4; ++j) {
        int dc = wn*32 + j*8 + lt*2;
        __nv_bfloat16* p0 = ob + (size_t)(b*NN + q0 + r0) * CC + h*DD + dc;
        __nv_bfloat16* p1 = ob + (size_t)(b*NN + q0 + r0 + 8) * CC + h*DD + dc;
        *(__nv_bfloat162*)p0 = __floats2bfloat162_rn(o[j][0]*i0, o[j][1]*i0);
        *(__nv_bfloat162*)p1 = __floats2bfloat162_rn(o[j][2]*i1, o[j][3]*i1);
    }
}

// ---------------- launch ----------------
#define GSMEM128 98304
#define GSMEM64  73728
extern "C" void kernel_launch(void* const* d_in, const int* in_sizes, int n_in,
                              void* d_out, int out_size)
{
    const float* x        = (const float*)d_in[0];
    const int*   rpi      = (const int*)  d_in[2];
    const float* W_qkv    = (const float*)d_in[3];
    const float* W_proj   = (const float*)d_in[4];
    const float* b_proj   = (const float*)d_in[5];
    const float* rel_tab  = (const float*)d_in[6];
    const float* ln1_g    = (const float*)d_in[7];
    const float* ln1_b    = (const float*)d_in[8];
    const float* gamma1   = (const float*)d_in[9];
    const float* gamma2   = (const float*)d_in[10];
    const float* ln2t_g   = (const float*)d_in[11];
    const float* ln2t_b   = (const float*)d_in[12];
    const float* fc1t_W   = (const float*)d_in[13];
    const float* fc1t_b   = (const float*)d_in[14];
    const float* fc2t_W   = (const float*)d_in[15];
    const float* fc2t_b   = (const float*)d_in[16];
    const float* ln2f_g   = (const float*)d_in[17];
    const float* ln2f_b   = (const float*)d_in[18];
    const float* fc1f_W   = (const float*)d_in[19];
    const float* fc1f_b   = (const float*)d_in[20];
    const float* fc2f_W   = (const float*)d_in[21];
    const float* fc2f_b   = (const float*)d_in[22];
    float* out = (float*)d_out;

    __nv_bfloat16 *hb, *qkvb, *ob, *h2b, *hidb, *biasb, *wqkv, *wproj, *w1t, *w1f, *w2t, *w2f;
    float* part;
    cudaGetSymbolAddress((void**)&hb,    g_hb);
    cudaGetSymbolAddress((void**)&qkvb,  g_qkvb);
    cudaGetSymbolAddress((void**)&ob,    g_ob);
    cudaGetSymbolAddress((void**)&h2b,   g_h2b);
    cudaGetSymbolAddress((void**)&hidb,  g_hidb);
    cudaGetSymbolAddress((void**)&biasb, g_biasb);
    cudaGetSymbolAddress((void**)&part,  g_part);
    cudaGetSymbolAddress((void**)&wqkv,  g_wqkv);
    cudaGetSymbolAddress((void**)&wproj, g_wproj);
    cudaGetSymbolAddress((void**)&w1t,   g_w1t);
    cudaGetSymbolAddress((void**)&w1f,   g_w1f);
    cudaGetSymbolAddress((void**)&w2t,   g_w2t);
    cudaGetSymbolAddress((void**)&w2f,   g_w2f);

    cudaFuncSetAttribute(mma_gemm<0,true,128>,  cudaFuncAttributeMaxDynamicSharedMemorySize, GSMEM128);
    cudaFuncSetAttribute(mma_gemm<1,false,64>,  cudaFuncAttributeMaxDynamicSharedMemorySize, GSMEM64);
    cudaFuncSetAttribute(mma_gemm<2,true,128>,  cudaFuncAttributeMaxDynamicSharedMemorySize, GSMEM128);
    cudaFuncSetAttribute(mma_gemm<4,false,128>, cudaFuncAttributeMaxDynamicSharedMemorySize, GSMEM128);
    cudaFuncSetAttribute(attn_fa,               cudaFuncAttributeMaxDynamicSharedMemorySize, FASMEM);

    static cudaStream_t s1 = [](){
        cudaStream_t s; cudaStreamCreateWithFlags(&s, cudaStreamNonBlocking); return s; }();
    static cudaEvent_t ev0 = [](){
        cudaEvent_t e; cudaEventCreateWithFlags(&e, cudaEventDisableTiming); return e; }();
    static cudaEvent_t evA = [](){
        cudaEvent_t e; cudaEventCreateWithFlags(&e, cudaEventDisableTiming); return e; }();
    static cudaEvent_t evBias = [](){
        cudaEvent_t e; cudaEventCreateWithFlags(&e, cudaEventDisableTiming); return e; }();
    static cudaEvent_t evB = [](){
        cudaEvent_t e; cudaEventCreateWithFlags(&e, cudaEventDisableTiming); return e; }();

    cudaEventRecord(ev0, 0);
    cudaStreamWaitEvent(s1, ev0, 0);

    cvt_a<<<(CA1 + 255)/256, 256, 0, s1>>>(
        (const float4*)W_qkv, (const float4*)W_proj,
        (__nv_bfloat162*)wqkv, (__nv_bfloat162*)wproj);
    cudaEventRecord(evA, s1);
    bias_kernel<<<NN*NN/256, 256, 0, s1>>>(rpi, rel_tab, biasb);
    cudaEventRecord(evBias, s1);
    cvt_b<<<(4*CB0 + 255)/256, 256, 0, s1>>>(
        (const float4*)fc1t_W, (const float4*)fc1f_W,
        (const float4*)fc2t_W, (const float4*)fc2f_W,
        (__nv_bfloat162*)w1t, (__nv_bfloat162*)w1f,
        (__nv_bfloat162*)w2t, (__nv_bfloat162*)w2f);
    cudaEventRecord(evB, s1);

    // LN1 (2 rows/CTA)
    ln_kernel<<<M_TOK/2, 384>>>((const float4*)x, (uint2*)hb,
        (const float4*)ln1_g, (const float4*)ln1_b, nullptr, nullptr, 0);

    // QKV
    cudaStreamWaitEvent(0, evA, 0);
    mma_gemm<4,false,128><<<dim3(3*CC/128, M_TOK/128), 256, GSMEM128>>>(
        hb, CC, CC, 3*CC, wqkv, nullptr, nullptr, nullptr, nullptr, nullptr, nullptr, qkvb);

    // attention
    cudaStreamWaitEvent(0, evBias, 0);
    attn_fa<<<dim3(NN/64, HH, BB), 256, FASMEM>>>(qkvb, biasb, ob);

    // proj (BN=64 tiles for finer waves)
    mma_gemm<1,false,64><<<dim3(CC/64, M_TOK/128), 256, GSMEM64>>>(
        ob, CC, CC, CC, wproj, nullptr, b_proj, nullptr, x, gamma1, out, nullptr);

    // LN2
    ln_kernel<<<M_TOK/2, 384>>>((const float4*)out, (uint2*)h2b,
        (const float4*)ln2t_g, (const float4*)ln2t_b,
        (const float4*)ln2f_g, (const float4*)ln2f_b, 1);

    // fc1 + gelu
    cudaStreamWaitEvent(0, evB, 0);
    mma_gemm<2,true,128><<<dim3(HID/128, M_TOK/128), 256, GSMEM128>>>(
        h2b, CC, CC, HID, w1t, w1f, fc1t_b, fc1f_b, nullptr, nullptr, nullptr, hidb);

    // fc2 split-K=3 -> fp32 partials
    mma_gemm<0,true,128><<<dim3(CC/128, M_TOK/128, 3), 256, GSMEM128>>>(
        hidb, HID/3, HID, CC, w2t, w2f, nullptr, nullptr, nullptr, nullptr, part, nullptr);

    // fc2 reduce
    fc2_reduce<<<M_TOK*CC/1024, 256>>>(part, fc2t_b, fc2f_b, gamma2, out);
}

// round 13
// speedup vs baseline: 1.0159x; 1.0159x over previous
#include <cuda_runtime.h>
#include <cuda_bf16.h>
#include <math.h>
#include <stdint.h>

// Problem constants
#define BB   16
#define NN   512
#define CC   768
#define HH   12
#define DD   64
#define HID  3072
#define M_TOK (BB*NN)          // 8192

// ---------------- scratch (device globals; no allocations) ----------------
__device__ __nv_bfloat16 g_hb  [M_TOK * CC];
__device__ __nv_bfloat16 g_qkvb[M_TOK * 3*CC];
__device__ __nv_bfloat16 g_ob  [M_TOK * CC];
__device__ __nv_bfloat16 g_h2b [M_TOK * CC];
__device__ __nv_bfloat16 g_hidb[M_TOK * HID];
__device__ __nv_bfloat16 g_biasb[HH * NN * NN];  // rel-pos bias (x log2e)
__device__ float         g_part[2 * M_TOK * CC]; // fc2 split-K partials
// bf16 weights
__device__ __nv_bfloat16 g_wqkv [3*CC*CC];
__device__ __nv_bfloat16 g_wproj[CC*CC];
__device__ __nv_bfloat16 g_w1t  [HID*CC];
__device__ __nv_bfloat16 g_w1f  [HID*CC];
__device__ __nv_bfloat16 g_w2t  [CC*HID];
__device__ __nv_bfloat16 g_w2f  [CC*HID];

// ---------------- PTX helpers ----------------
__device__ __forceinline__ uint32_t smem_u32(const void* p) {
    uint32_t a;
    asm("{ .reg .u64 t; cvta.to.shared.u64 t, %1; cvt.u32.u64 %0, t; }" : "=r"(a) : "l"(p));
    return a;
}
__device__ __forceinline__ float ex2f(float x) {
    float r;
    asm("ex2.approx.ftz.f32 %0, %1;" : "=f"(r) : "f"(x));
    return r;
}
#define CP16(dst, src) \
    asm volatile("cp.async.cg.shared.global [%0], [%1], 16;" :: "r"(dst), "l"(src))
#define CPCOMMIT() asm volatile("cp.async.commit_group;" ::: "memory")
#define CPWAIT(n)  asm volatile("cp.async.wait_group %0;" :: "n"(n) : "memory")
#define LDSM4(r0, r1, r2, r3, addr) \
    asm volatile("ldmatrix.sync.aligned.m8n8.x4.shared.b16 {%0,%1,%2,%3}, [%4];" \
        : "=r"(r0), "=r"(r1), "=r"(r2), "=r"(r3) : "r"(addr))
#define LDSM4T(r0, r1, r2, r3, addr) \
    asm volatile("ldmatrix.sync.aligned.m8n8.x4.trans.shared.b16 {%0,%1,%2,%3}, [%4];" \
        : "=r"(r0), "=r"(r1), "=r"(r2), "=r"(r3) : "r"(addr))
#define MMA16816(c, a, b) \
    asm volatile("mma.sync.aligned.m16n8k16.row.col.f32.bf16.bf16.f32 " \
        "{%0,%1,%2,%3}, {%4,%5,%6,%7}, {%8,%9}, {%0,%1,%2,%3};" \
        : "+f"((c)[0]), "+f"((c)[1]), "+f"((c)[2]), "+f"((c)[3]) \
        : "r"((a)[0]), "r"((a)[1]), "r"((a)[2]), "r"((a)[3]), "r"((b)[0]), "r"((b)[1]))

#define SW128(row, ch) ((uint32_t)((row)*128 + ((((ch) ^ ((row)&7))) << 4)))

// ---------------- fp32 -> bf16 weight converts (two batches) ----------------
#define CA0 442368
#define CA1 (CA0 + 147456)
__global__ __launch_bounds__(256)
void cvt_a(const float4* __restrict__ s0, const float4* __restrict__ s1,
           __nv_bfloat162* __restrict__ d0, __nv_bfloat162* __restrict__ d1)
{
    int i = blockIdx.x * 256 + threadIdx.x;
    if (i >= CA1) return;
    const float4* s; __nv_bfloat162* d; int off;
    if (i < CA0) { s = s0; d = d0; off = i; }
    else         { s = s1; d = d1; off = i - CA0; }
    float4 v = s[off];
    d[2*off]   = __floats2bfloat162_rn(v.x, v.y);
    d[2*off+1] = __floats2bfloat162_rn(v.z, v.w);
}
#define CB0 589824
__global__ __launch_bounds__(256)
void cvt_b(const float4* __restrict__ s0, const float4* __restrict__ s1,
           const float4* __restrict__ s2, const float4* __restrict__ s3,
           __nv_bfloat162* __restrict__ d0, __nv_bfloat162* __restrict__ d1,
           __nv_bfloat162* __restrict__ d2, __nv_bfloat162* __restrict__ d3)
{
    int i = blockIdx.x * 256 + threadIdx.x;
    if (i >= 4*CB0) return;
    int seg = i / CB0, off = i - seg*CB0;
    const float4* s = (seg == 0) ? s0 : (seg == 1) ? s1 : (seg == 2) ? s2 : s3;
    __nv_bfloat162* d = (seg == 0) ? d0 : (seg == 1) ? d1 : (seg == 2) ? d2 : d3;
    float4 v = s[off];
    d[2*off]   = __floats2bfloat162_rn(v.x, v.y);
    d[2*off+1] = __floats2bfloat162_rn(v.z, v.w);
}

// ---------------- rel-pos bias precompute ----------------
__global__ __launch_bounds__(256)
void bias_kernel(const int* __restrict__ rpi, const float* __restrict__ table,
                 __nv_bfloat16* __restrict__ out)
{
    int e = blockIdx.x * 256 + threadIdx.x;
    int idx = rpi[e];
    const float* t = table + (size_t)idx * HH;
    #pragma unroll
    for (int h = 0; h < HH; ++h)
        out[(size_t)h * (NN*NN) + e] = __float2bfloat16(t[h] * 1.4426950408889634f);
}

// ---------------- LayerNorm (vectorized, bf16 output) ----------------
__global__ __launch_bounds__(192)
void ln_kernel(const float4* __restrict__ x4, uint2* __restrict__ out,
               const float4* __restrict__ g0, const float4* __restrict__ b0,
               const float4* __restrict__ g1, const float4* __restrict__ b1,
               int split)
{
    int m = blockIdx.x;
    int t = threadIdx.x;
    float4 v = x4[(size_t)m * 192 + t];
    float s  = (v.x + v.y) + (v.z + v.w);
    float sq = (v.x*v.x + v.y*v.y) + (v.z*v.z + v.w*v.w);

    __shared__ float r1[6], r2[6];
    #pragma unroll
    for (int o = 16; o; o >>= 1) {
        s  += __shfl_xor_sync(0xffffffffu, s,  o);
        sq += __shfl_xor_sync(0xffffffffu, sq, o);
    }
    if ((t & 31) == 0) { r1[t >> 5] = s; r2[t >> 5] = sq; }
    __syncthreads();
    float tot = 0.f, totq = 0.f;
    #pragma unroll
    for (int i = 0; i < 6; i++) { tot += r1[i]; totq += r2[i]; }
    float mean = tot * (1.f / CC);
    float var  = totq * (1.f / CC) - mean * mean;
    float inv  = rsqrtf(var + 1e-5f);

    const float4* g = g0; const float4* bb = b0;
    if (split && (m & (NN - 1)) >= 256) { g = g1; bb = b1; }
    float4 gv = g[t], bv = bb[t];
    float o0 = (v.x - mean) * inv * gv.x + bv.x;
    float o1 = (v.y - mean) * inv * gv.y + bv.y;
    float o2 = (v.z - mean) * inv * gv.z + bv.z;
    float o3 = (v.w - mean) * inv * gv.w + bv.w;
    __nv_bfloat162 p0 = __floats2bfloat162_rn(o0, o1);
    __nv_bfloat162 p1 = __floats2bfloat162_rn(o2, o3);
    out[(size_t)m * 192 + t] = make_uint2(*(uint32_t*)&p0, *(uint32_t*)&p1);
}

// ---------------- HMMA bf16 GEMM (round-7 proven mainloop, BN=128) --------
#define GSMEM 98304
template<int EPI, bool SPLIT>
__global__ __launch_bounds__(256, 2)
void mma_gemm(const __nv_bfloat16* __restrict__ A, int K, int ldk, int N,
              const __nv_bfloat16* __restrict__ W0, const __nv_bfloat16* __restrict__ W1,
              const float* __restrict__ bias0, const float* __restrict__ bias1,
              const float* __restrict__ res, const float* __restrict__ gamma,
              float* __restrict__ outf, __nv_bfloat16* __restrict__ outb)
{
    extern __shared__ char gsm[];
    const int m0 = blockIdx.y * 128;
    const int n0 = blockIdx.x * 128;
    const int koff = blockIdx.z * K;
    const __nv_bfloat16* W = W0;
    const float* bias = bias0;
    if (SPLIT && ((m0 & (NN - 1)) >= 256)) { W = W1; bias = bias1; }

    const int tid  = threadIdx.x;
    const int lane = tid & 31;
    const int wid  = tid >> 5;
    const int wm   = wid >> 1;
    const int wn   = wid & 1;

    const uint32_t asb = smem_u32(gsm);
    const uint32_t bsb = asb + 16384u;

    const int lrow = tid >> 3;
    const int lch  = tid & 7;

    float c[2][8][4];
    #pragma unroll
    for (int i = 0; i < 2; i++)
        #pragma unroll
        for (int j = 0; j < 8; j++)
            #pragma unroll
            for (int q = 0; q < 4; q++) c[i][j][q] = 0.f;

    const int nk = K >> 6;

    auto issue = [&](int kc, int stg) {
        const __nv_bfloat16* Ap = A + koff + (size_t)m0 * ldk + kc*64;
        const __nv_bfloat16* Wp = W + koff + (size_t)n0 * ldk + kc*64;
        const uint32_t ao = asb + (uint32_t)stg * 32768u;
        const uint32_t bo = bsb + (uint32_t)stg * 32768u;
        #pragma unroll
        for (int it = 0; it < 4; ++it) {
            int row = it*32 + lrow;
            CP16(ao + SW128(row, lch), Ap + (size_t)row * ldk + lch*8);
            CP16(bo + SW128(row, lch), Wp + (size_t)row * ldk + lch*8);
        }
    };

    issue(0, 0); CPCOMMIT();
    if (nk > 1) issue(1, 1);
    CPCOMMIT();

    for (int kc = 0; kc < nk; ++kc) {
        if (kc + 2 < nk) issue(kc + 2, (kc + 2) % 3);
        CPCOMMIT();
        CPWAIT(2);
        __syncthreads();

        const uint32_t ab = asb + (uint32_t)(kc % 3) * 32768u;
        const uint32_t bb = bsb + (uint32_t)(kc % 3) * 32768u;
        #pragma unroll
        for (int kk = 0; kk < 4; ++kk) {
            uint32_t a[2][4];
            #pragma unroll
            for (int i = 0; i < 2; ++i) {
                int row = wm*32 + i*16 + (lane & 7) + ((lane >> 3) & 1) * 8;
                int ch  = 2*kk + (lane >> 4);
                LDSM4(a[i][0], a[i][1], a[i][2], a[i][3], ab + SW128(row, ch));
            }
            uint32_t b[8][2];
            #pragma unroll
            for (int jp = 0; jp < 4; ++jp) {
                int row = wn*64 + jp*16 + (lane & 7) + (lane >> 4) * 8;
                int ch  = 2*kk + ((lane >> 3) & 1);
                uint32_t t0, t1, t2, t3;
                LDSM4(t0, t1, t2, t3, bb + SW128(row, ch));
                b[jp*2][0] = t0; b[jp*2][1] = t1;
                b[jp*2+1][0] = t2; b[jp*2+1][1] = t3;
            }
            #pragma unroll
            for (int i = 0; i < 2; ++i)
                #pragma unroll
                for (int j = 0; j < 8; ++j)
                    MMA16816(c[i][j], a[i], b[j]);
        }
        __syncthreads();
    }

    float* outz = (EPI == 0) ? (outf + (size_t)blockIdx.z * M_TOK * N) : outf;
    const int g  = lane >> 2;
    const int t4 = lane & 3;
    #pragma unroll
    for (int i = 0; i < 2; ++i) {
        #pragma unroll
        for (int half = 0; half < 2; ++half) {
            const int m = m0 + wm*32 + i*16 + g + half*8;
            #pragma unroll
            for (int j = 0; j < 8; ++j) {
                const int n = n0 + wn*64 + j*8 + t4*2;
                const float v0 = c[i][j][half*2+0];
                const float v1 = c[i][j][half*2+1];
                const size_t idx = (size_t)m * N + n;
                if (EPI == 0) {
                    *(float2*)(outz + idx) = make_float2(v0, v1);
                } else if (EPI == 1) {
                    float ga = __ldg(gamma + n), gb = __ldg(gamma + n + 1);
                    float ba = __ldg(bias + n),  bbv = __ldg(bias + n + 1);
                    float ra = __ldg(res + idx), rb = __ldg(res + idx + 1);
                    *(float2*)(outf + idx) = make_float2(ra + ga*(v0 + ba), rb + gb*(v1 + bbv));
                } else if (EPI == 2) {
                    float x0 = v0 + __ldg(bias + n);
                    float x1 = v1 + __ldg(bias + n + 1);
                    float e0 = 0.5f * x0 * (1.f + erff(x0 * 0.70710678118654752440f));
                    float e1 = 0.5f * x1 * (1.f + erff(x1 * 0.70710678118654752440f));
                    *(__nv_bfloat162*)(outb + idx) = __floats2bfloat162_rn(e0, e1);
                } else { // EPI == 4
                    *(__nv_bfloat162*)(outb + idx) = __floats2bfloat162_rn(v0, v1);
                }
            }
        }
    }
}

// ---------------- fc2 split-K=2 reduce ----------------
__global__ __launch_bounds__(256)
void fc2_reduce(const float* __restrict__ part, const float* __restrict__ bt,
                const float* __restrict__ bf, const float* __restrict__ gamma,
                float* __restrict__ out)
{
    int i = blockIdx.x * 256 + threadIdx.x;
    size_t idx = (size_t)i * 4;
    int m = (int)(idx / CC);
    int n = (int)(idx % CC);
    const float* bias = ((m & (NN - 1)) >= 256) ? bf : bt;
    float4 p0 = *(const float4*)(part + idx);
    float4 p1 = *(const float4*)(part + (size_t)M_TOK*CC + idx);
    float4 o  = *(const float4*)(out + idx);
    float4 gm = *(const float4*)(gamma + n);
    float4 bs = *(const float4*)(bias + n);
    o.x += gm.x * (p0.x + p1.x + bs.x);
    o.y += gm.y * (p0.y + p1.y + bs.y);
    o.z += gm.z * (p0.z + p1.z + bs.z);
    o.w += gm.w * (p0.w + p1.w + bs.w);
    *(float4*)(out + idx) = o;
}

// ---------------- FlashAttention: register-resident P, k-split PV ----------
// grid (8, H, B): block = 64 q rows. 256 threads, 8 warps (wm 0..3 rows,
// wn 0..1 = 64-col/64-k half). P never touches smem: QK C-frags are reused
// directly as PV A-frags; each wn warp reduces its own 64-k half and the two
// halves merge once at the end. KV ring = 4 buffers -> single sync per tile.
// smem: Q 8K @0, KV 4x16K @8192, O-merge 64x68 f32 @73728, l 64 f32x2 @91136.
#define FA_Q   0u
#define FA_KV  8192u
#define FA_MRG 73728u
#define FA_LB  91136u
#define FASMEM 91648
__global__ __launch_bounds__(256, 2)
void attn_fa(const __nv_bfloat16* __restrict__ qkvb, const __nv_bfloat16* __restrict__ biasb,
             __nv_bfloat16* __restrict__ ob)
{
    extern __shared__ char sm[];
    const uint32_t sb = smem_u32(sm);
    float* mrg  = (float*)(sm + FA_MRG);   // pitch 68
    float* lbuf = (float*)(sm + FA_LB);

    const int q0 = blockIdx.x * 64;
    const int h  = blockIdx.y;
    const int b  = blockIdx.z;
    const int tid = threadIdx.x;
    const int lane = tid & 31;
    const int wid  = tid >> 5;
    const int wm   = wid >> 1;   // 0..3: 16 q-rows
    const int wn   = wid & 1;    // 0..1: KV col-half / k-half
    const int lq   = lane >> 2;
    const int lt   = lane & 3;
    const int r0   = wm*16 + lq;

    const __nv_bfloat16* brow = biasb + (size_t)h * (NN*NN);
    const float LOG2E_SCALE = 0.125f * 1.4426950408889634f;

    auto issueT = [&](int tile, int co, int bufi) {
        uint32_t base = sb + FA_KV + (uint32_t)bufi * 16384u;
        #pragma unroll
        for (int it = 0; it < 4; ++it) {
            int e = it*256 + tid;
            int row = e >> 3, ch = e & 7;
            CP16(base + SW128(row, ch),
                 qkvb + (size_t)(b*NN + tile*128 + row) * (3*CC) + co + h*DD + ch*8);
        }
    };

    // prologue: Q + K0 (group 0), V0 (group 1)
    #pragma unroll
    for (int it = 0; it < 2; ++it) {
        int e = it*256 + tid;
        int row = e >> 3, ch = e & 7;
        CP16(sb + FA_Q + SW128(row, ch),
             qkvb + (size_t)(b*NN + q0 + row) * (3*CC) + h*DD + ch*8);
    }
    issueT(0, CC, 0);
    CPCOMMIT();
    issueT(0, 2*CC, 1);
    CPCOMMIT();

    float o[8][4];
    #pragma unroll
    for (int j = 0; j < 8; ++j)
        #pragma unroll
        for (int q = 0; q < 4; ++q) o[j][q] = 0.f;
    float l0r = 0.f, l1r = 0.f;

    for (int t = 0; t < 4; ++t) {
        CPWAIT(1);            // K_t ready
        __syncthreads();      // all warps done with tile t-1 (buffers reusable)
        if (t < 3) { issueT(t + 1, CC, (2*t + 2) & 3); CPCOMMIT(); }
        const uint32_t kbase = sb + FA_KV + (uint32_t)((2*t) & 3) * 16384u;
        const uint32_t vbase = sb + FA_KV + (uint32_t)((2*t + 1) & 3) * 16384u;

        // ---- S = Q K^T (warp: 16 rows x 64 cols, cols wn*64..) ----
        float s[8][4];
        #pragma unroll
        for (int j = 0; j < 8; ++j)
            #pragma unroll
            for (int q = 0; q < 4; ++q) s[j][q] = 0.f;
        #pragma unroll
        for (int kk = 0; kk < 4; ++kk) {
            uint32_t a[4];
            {
                int row = wm*16 + (lane & 7) + ((lane >> 3) & 1) * 8;
                int ch  = 2*kk + (lane >> 4);
                LDSM4(a[0], a[1], a[2], a[3], sb + FA_Q + SW128(row, ch));
            }
            uint32_t bfr[8][2];
            #pragma unroll
            for (int jp = 0; jp < 4; ++jp) {
                int row = wn*64 + jp*16 + (lane & 7) + (lane >> 4) * 8;
                int ch  = 2*kk + ((lane >> 3) & 1);
                uint32_t t0, t1, t2, t3;
                LDSM4(t0, t1, t2, t3, kbase + SW128(row, ch));
                bfr[jp*2][0] = t0; bfr[jp*2][1] = t1;
                bfr[jp*2+1][0] = t2; bfr[jp*2+1][1] = t3;
            }
            #pragma unroll
            for (int j = 0; j < 8; ++j)
                MMA16816(s[j], a, bfr[j]);
        }

        // ---- p = 2^(s*scale + bias); pack in registers; local row sums ----
        uint32_t pb[8][2];
        #pragma unroll
        for (int j = 0; j < 8; ++j) {
            int cg = t*128 + wn*64 + j*8 + lt*2;
            __nv_bfloat162 b0 = *(const __nv_bfloat162*)(brow + (size_t)(q0 + r0) * NN + cg);
            __nv_bfloat162 b1 = *(const __nv_bfloat162*)(brow + (size_t)(q0 + r0 + 8) * NN + cg);
            float p0 = ex2f(fmaf(s[j][0], LOG2E_SCALE, __bfloat162float(b0.x)));
            float p1 = ex2f(fmaf(s[j][1], LOG2E_SCALE, __bfloat162float(b0.y)));
            float p2 = ex2f(fmaf(s[j][2], LOG2E_SCALE, __bfloat162float(b1.x)));
            float p3 = ex2f(fmaf(s[j][3], LOG2E_SCALE, __bfloat162float(b1.y)));
            l0r += p0 + p1;
            l1r += p2 + p3;
            __nv_bfloat162 q01 = __floats2bfloat162_rn(p0, p1);
            __nv_bfloat162 q23 = __floats2bfloat162_rn(p2, p3);
            pb[j][0] = *(uint32_t*)&q01;
            pb[j][1] = *(uint32_t*)&q23;
        }

        // ---- wait V_t; PV over this warp's 64-k half, all 64 d-cols ----
        if (t < 3) { CPWAIT(1); } else { CPWAIT(0); }
        #pragma unroll
        for (int kk = 0; kk < 4; ++kk) {
            uint32_t a[4] = { pb[2*kk][0], pb[2*kk][1], pb[2*kk+1][0], pb[2*kk+1][1] };
            #pragma unroll
            for (int j2 = 0; j2 < 4; ++j2) {
                int krow = wn*64 + kk*16 + (lane & 7) + ((lane >> 3) & 1) * 8;
                int ch   = j2*2 + (lane >> 4);
                uint32_t t0, t1, t2, t3;
                LDSM4T(t0, t1, t2, t3, vbase + SW128(krow, ch));
                uint32_t bv0[2] = {t0, t1}, bv1[2] = {t2, t3};
                MMA16816(o[j2*2],     a, bv0);
                MMA16816(o[j2*2 + 1], a, bv1);
            }
        }
        if (t < 3) { issueT(t + 1, 2*CC, (2*t + 3) & 3); CPCOMMIT(); }
    }

    // ---- merge the two k-halves + l, then write O = acc / l ----
    l0r += __shfl_xor_sync(0xffffffffu, l0r, 1);
    l0r += __shfl_xor_sync(0xffffffffu, l0r, 2);
    l1r += __shfl_xor_sync(0xffffffffu, l1r, 1);
    l1r += __shfl_xor_sync(0xffffffffu, l1r, 2);

    if (wn == 1) {
        #pragma unroll
        for (int j = 0; j < 8; ++j) {
            *(float2*)(mrg + r0*68 + j*8 + lt*2)       = make_float2(o[j][0], o[j][1]);
            *(float2*)(mrg + (r0 + 8)*68 + j*8 + lt*2) = make_float2(o[j][2], o[j][3]);
        }
        if (lt == 0) { lbuf[r0] = l0r; lbuf[r0 + 8] = l1r; }
    }
    __syncthreads();
    if (wn == 0) {
        float i0 = 1.f / (l0r + lbuf[r0]);
        float i1 = 1.f / (l1r + lbuf[r0 + 8]);
        #pragma unroll
        for (int j = 0; j < 8; ++j) {
            float2 m0 = *(float2*)(mrg + r0*68 + j*8 + lt*2);
            float2 m1 = *(float2*)(mrg + (r0 + 8)*68 + j*8 + lt*2);
            int dc = j*8 + lt*2;
            __nv_bfloat16* p0 = ob + (size_t)(b*NN + q0 + r0) * CC + h*DD + dc;
            __nv_bfloat16* p1 = ob + (size_t)(b*NN + q0 + r0 + 8) * CC + h*DD + dc;
            *(__nv_bfloat162*)p0 = __floats2bfloat162_rn((o[j][0] + m0.x)*i0, (o[j][1] + m0.y)*i0);
            *(__nv_bfloat162*)p1 = __floats2bfloat162_rn((o[j][2] + m1.x)*i1, (o[j][3] + m1.y)*i1);
        }
    }
}

// ---------------- launch ----------------
extern "C" void kernel_launch(void* const* d_in, const int* in_sizes, int n_in,
                              void* d_out, int out_size)
{
    const float* x        = (const float*)d_in[0];
    const int*   rpi      = (const int*)  d_in[2];
    const float* W_qkv    = (const float*)d_in[3];
    const float* W_proj   = (const float*)d_in[4];
    const float* b_proj   = (const float*)d_in[5];
    const float* rel_tab  = (const float*)d_in[6];
    const float* ln1_g    = (const float*)d_in[7];
    const float* ln1_b    = (const float*)d_in[8];
    const float* gamma1   = (const float*)d_in[9];
    const float* gamma2   = (const float*)d_in[10];
    const float* ln2t_g   = (const float*)d_in[11];
    const float* ln2t_b   = (const float*)d_in[12];
    const float* fc1t_W   = (const float*)d_in[13];
    const float* fc1t_b   = (const float*)d_in[14];
    const float* fc2t_W   = (const float*)d_in[15];
    const float* fc2t_b   = (const float*)d_in[16];
    const float* ln2f_g   = (const float*)d_in[17];
    const float* ln2f_b   = (const float*)d_in[18];
    const float* fc1f_W   = (const float*)d_in[19];
    const float* fc1f_b   = (const float*)d_in[20];
    const float* fc2f_W   = (const float*)d_in[21];
    const float* fc2f_b   = (const float*)d_in[22];
    float* out = (float*)d_out;

    __nv_bfloat16 *hb, *qkvb, *ob, *h2b, *hidb, *biasb, *wqkv, *wproj, *w1t, *w1f, *w2t, *w2f;
    float* part;
    cudaGetSymbolAddress((void**)&hb,    g_hb);
    cudaGetSymbolAddress((void**)&qkvb,  g_qkvb);
    cudaGetSymbolAddress((void**)&ob,    g_ob);
    cudaGetSymbolAddress((void**)&h2b,   g_h2b);
    cudaGetSymbolAddress((void**)&hidb,  g_hidb);
    cudaGetSymbolAddress((void**)&biasb, g_biasb);
    cudaGetSymbolAddress((void**)&part,  g_part);
    cudaGetSymbolAddress((void**)&wqkv,  g_wqkv);
    cudaGetSymbolAddress((void**)&wproj, g_wproj);
    cudaGetSymbolAddress((void**)&w1t,   g_w1t);
    cudaGetSymbolAddress((void**)&w1f,   g_w1f);
    cudaGetSymbolAddress((void**)&w2t,   g_w2t);
    cudaGetSymbolAddress((void**)&w2f,   g_w2f);

    cudaFuncSetAttribute(mma_gemm<0,true>,  cudaFuncAttributeMaxDynamicSharedMemorySize, GSMEM);
    cudaFuncSetAttribute(mma_gemm<1,false>, cudaFuncAttributeMaxDynamicSharedMemorySize, GSMEM);
    cudaFuncSetAttribute(mma_gemm<2,true>,  cudaFuncAttributeMaxDynamicSharedMemorySize, GSMEM);
    cudaFuncSetAttribute(mma_gemm<4,false>, cudaFuncAttributeMaxDynamicSharedMemorySize, GSMEM);
    cudaFuncSetAttribute(attn_fa,           cudaFuncAttributeMaxDynamicSharedMemorySize, FASMEM);

    static cudaStream_t s1 = [](){
        cudaStream_t s; cudaStreamCreateWithFlags(&s, cudaStreamNonBlocking); return s; }();
    static cudaEvent_t ev0 = [](){
        cudaEvent_t e; cudaEventCreateWithFlags(&e, cudaEventDisableTiming); return e; }();
    static cudaEvent_t evA = [](){
        cudaEvent_t e; cudaEventCreateWithFlags(&e, cudaEventDisableTiming); return e; }();
    static cudaEvent_t evBias = [](){
        cudaEvent_t e; cudaEventCreateWithFlags(&e, cudaEventDisableTiming); return e; }();
    static cudaEvent_t evB = [](){
        cudaEvent_t e; cudaEventCreateWithFlags(&e, cudaEventDisableTiming); return e; }();

    cudaEventRecord(ev0, 0);
    cudaStreamWaitEvent(s1, ev0, 0);

    cvt_a<<<(CA1 + 255)/256, 256, 0, s1>>>(
        (const float4*)W_qkv, (const float4*)W_proj,
        (__nv_bfloat162*)wqkv, (__nv_bfloat162*)wproj);
    cudaEventRecord(evA, s1);
    bias_kernel<<<NN*NN/256, 256, 0, s1>>>(rpi, rel_tab, biasb);
    cudaEventRecord(evBias, s1);
    cvt_b<<<(4*CB0 + 255)/256, 256, 0, s1>>>(
        (const float4*)fc1t_W, (const float4*)fc1f_W,
        (const float4*)fc2t_W, (const float4*)fc2f_W,
        (__nv_bfloat162*)w1t, (__nv_bfloat162*)w1f,
        (__nv_bfloat162*)w2t, (__nv_bfloat162*)w2f);
    cudaEventRecord(evB, s1);

    // LN1
    ln_kernel<<<M_TOK, 192>>>((const float4*)x, (uint2*)hb,
        (const float4*)ln1_g, (const float4*)ln1_b, nullptr, nullptr, 0);

    // QKV
    cudaStreamWaitEvent(0, evA, 0);
    mma_gemm<4,false><<<dim3(3*CC/128, M_TOK/128), 256, GSMEM>>>(
        hb, CC, CC, 3*CC, wqkv, nullptr, nullptr, nullptr, nullptr, nullptr, nullptr, qkvb);

    // attention
    cudaStreamWaitEvent(0, evBias, 0);
    attn_fa<<<dim3(NN/64, HH, BB), 256, FASMEM>>>(qkvb, biasb, ob);

    // proj
    mma_gemm<1,false><<<dim3(CC/128, M_TOK/128), 256, GSMEM>>>(
        ob, CC, CC, CC, wproj, nullptr, b_proj, nullptr, x, gamma1, out, nullptr);

    // LN2
    ln_kernel<<<M_TOK, 192>>>((const float4*)out, (uint2*)h2b,
        (const float4*)ln2t_g, (const float4*)ln2t_b,
        (const float4*)ln2f_g, (const float4*)ln2f_b, 1);

    // fc1 + gelu
    cudaStreamWaitEvent(0, evB, 0);
    mma_gemm<2,true><<<dim3(HID/128, M_TOK/128), 256, GSMEM>>>(
        h2b, CC, CC, HID, w1t, w1f, fc1t_b, fc1f_b, nullptr, nullptr, nullptr, hidb);

    // fc2 split-K=2 -> fp32 partials
    mma_gemm<0,true><<<dim3(CC/128, M_TOK/128, 2), 256, GSMEM>>>(
        hidb, HID/2, HID, CC, w2t, w2f, nullptr, nullptr, nullptr, nullptr, part, nullptr);

    // fc2 reduce
    fc2_reduce<<<M_TOK*CC/1024, 256>>>(part, fc2t_b, fc2f_b, gamma2, out);
}

// round 14
// speedup vs baseline: 1.0961x; 1.0789x over previous
#include <cuda_runtime.h>
#include <cuda_bf16.h>
#include <math.h>
#include <stdint.h>

// Problem constants
#define BB   16
#define NN   512
#define CC   768
#define HH   12
#define DD   64
#define HID  3072
#define M_TOK (BB*NN)          // 8192

// ---------------- scratch (device globals; no allocations) ----------------
__device__ __nv_bfloat16 g_hb  [M_TOK * CC];
__device__ __nv_bfloat16 g_qkvb[M_TOK * 3*CC];
__device__ __nv_bfloat16 g_ob  [M_TOK * CC];
__device__ __nv_bfloat16 g_h2b [M_TOK * CC];
__device__ __nv_bfloat16 g_hidb[M_TOK * HID];
__device__ __nv_bfloat16 g_biasb[HH * NN * NN];  // rel-pos bias (x log2e)
__device__ float         g_part[2 * M_TOK * CC]; // fc2 split-K partials
// bf16 weights
__device__ __nv_bfloat16 g_wqkv [3*CC*CC];
__device__ __nv_bfloat16 g_wproj[CC*CC];
__device__ __nv_bfloat16 g_w1t  [HID*CC];
__device__ __nv_bfloat16 g_w1f  [HID*CC];
__device__ __nv_bfloat16 g_w2t  [CC*HID];
__device__ __nv_bfloat16 g_w2f  [CC*HID];

// ---------------- PTX helpers ----------------
__device__ __forceinline__ uint32_t smem_u32(const void* p) {
    uint32_t a;
    asm("{ .reg .u64 t; cvta.to.shared.u64 t, %1; cvt.u32.u64 %0, t; }" : "=r"(a) : "l"(p));
    return a;
}
__device__ __forceinline__ float ex2f(float x) {
    float r;
    asm("ex2.approx.ftz.f32 %0, %1;" : "=f"(r) : "f"(x));
    return r;
}
#define CP16(dst, src) \
    asm volatile("cp.async.cg.shared.global [%0], [%1], 16;" :: "r"(dst), "l"(src))
#define CPCOMMIT() asm volatile("cp.async.commit_group;" ::: "memory")
#define CPWAIT(n)  asm volatile("cp.async.wait_group %0;" :: "n"(n) : "memory")
#define LDSM4(r0, r1, r2, r3, addr) \
    asm volatile("ldmatrix.sync.aligned.m8n8.x4.shared.b16 {%0,%1,%2,%3}, [%4];" \
        : "=r"(r0), "=r"(r1), "=r"(r2), "=r"(r3) : "r"(addr))
#define LDSM4T(r0, r1, r2, r3, addr) \
    asm volatile("ldmatrix.sync.aligned.m8n8.x4.trans.shared.b16 {%0,%1,%2,%3}, [%4];" \
        : "=r"(r0), "=r"(r1), "=r"(r2), "=r"(r3) : "r"(addr))
#define MMA16816(c, a, b) \
    asm volatile("mma.sync.aligned.m16n8k16.row.col.f32.bf16.bf16.f32 " \
        "{%0,%1,%2,%3}, {%4,%5,%6,%7}, {%8,%9}, {%0,%1,%2,%3};" \
        : "+f"((c)[0]), "+f"((c)[1]), "+f"((c)[2]), "+f"((c)[3]) \
        : "r"((a)[0]), "r"((a)[1]), "r"((a)[2]), "r"((a)[3]), "r"((b)[0]), "r"((b)[1]))

#define SW128(row, ch) ((uint32_t)((row)*128 + ((((ch) ^ ((row)&7))) << 4)))

// ---------------- fp32 -> bf16 weight converts ----------------
#define CA0 442368
#define CA1 (CA0 + 147456)
__global__ __launch_bounds__(256)
void cvt_a(const float4* __restrict__ s0, const float4* __restrict__ s1,
           __nv_bfloat162* __restrict__ d0, __nv_bfloat162* __restrict__ d1)
{
    int i = blockIdx.x * 256 + threadIdx.x;
    if (i >= CA1) return;
    const float4* s; __nv_bfloat162* d; int off;
    if (i < CA0) { s = s0; d = d0; off = i; }
    else         { s = s1; d = d1; off = i - CA0; }
    float4 v = s[off];
    d[2*off]   = __floats2bfloat162_rn(v.x, v.y);
    d[2*off+1] = __floats2bfloat162_rn(v.z, v.w);
}
#define CB0 589824
__global__ __launch_bounds__(256)
void cvt_b(const float4* __restrict__ s0, const float4* __restrict__ s1,
           const float4* __restrict__ s2, const float4* __restrict__ s3,
           __nv_bfloat162* __restrict__ d0, __nv_bfloat162* __restrict__ d1,
           __nv_bfloat162* __restrict__ d2, __nv_bfloat162* __restrict__ d3)
{
    int i = blockIdx.x * 256 + threadIdx.x;
    if (i >= 4*CB0) return;
    int seg = i / CB0, off = i - seg*CB0;
    const float4* s = (seg == 0) ? s0 : (seg == 1) ? s1 : (seg == 2) ? s2 : s3;
    __nv_bfloat162* d = (seg == 0) ? d0 : (seg == 1) ? d1 : (seg == 2) ? d2 : d3;
    float4 v = s[off];
    d[2*off]   = __floats2bfloat162_rn(v.x, v.y);
    d[2*off+1] = __floats2bfloat162_rn(v.z, v.w);
}

// ---------------- rel-pos bias precompute ----------------
__global__ __launch_bounds__(256)
void bias_kernel(const int* __restrict__ rpi, const float* __restrict__ table,
                 __nv_bfloat16* __restrict__ out)
{
    int e = blockIdx.x * 256 + threadIdx.x;
    int idx = rpi[e];
    const float* t = table + (size_t)idx * HH;
    #pragma unroll
    for (int h = 0; h < HH; ++h)
        out[(size_t)h * (NN*NN) + e] = __float2bfloat16(t[h] * 1.4426950408889634f);
}

// ---------------- LayerNorm (vectorized, bf16 output, row offset) ----------
__global__ __launch_bounds__(192)
void ln_kernel(const float4* __restrict__ x4, uint2* __restrict__ out,
               const float4* __restrict__ g0, const float4* __restrict__ b0,
               const float4* __restrict__ g1, const float4* __restrict__ b1,
               int split, int moff)
{
    int m = blockIdx.x + moff;
    int t = threadIdx.x;
    float4 v = x4[(size_t)m * 192 + t];
    float s  = (v.x + v.y) + (v.z + v.w);
    float sq = (v.x*v.x + v.y*v.y) + (v.z*v.z + v.w*v.w);

    __shared__ float r1[6], r2[6];
    #pragma unroll
    for (int o = 16; o; o >>= 1) {
        s  += __shfl_xor_sync(0xffffffffu, s,  o);
        sq += __shfl_xor_sync(0xffffffffu, sq, o);
    }
    if ((t & 31) == 0) { r1[t >> 5] = s; r2[t >> 5] = sq; }
    __syncthreads();
    float tot = 0.f, totq = 0.f;
    #pragma unroll
    for (int i = 0; i < 6; i++) { tot += r1[i]; totq += r2[i]; }
    float mean = tot * (1.f / CC);
    float var  = totq * (1.f / CC) - mean * mean;
    float inv  = rsqrtf(var + 1e-5f);

    const float4* g = g0; const float4* bb = b0;
    if (split && (m & (NN - 1)) >= 256) { g = g1; bb = b1; }
    float4 gv = g[t], bv = bb[t];
    float o0 = (v.x - mean) * inv * gv.x + bv.x;
    float o1 = (v.y - mean) * inv * gv.y + bv.y;
    float o2 = (v.z - mean) * inv * gv.z + bv.z;
    float o3 = (v.w - mean) * inv * gv.w + bv.w;
    __nv_bfloat162 p0 = __floats2bfloat162_rn(o0, o1);
    __nv_bfloat162 p1 = __floats2bfloat162_rn(o2, o3);
    out[(size_t)m * 192 + t] = make_uint2(*(uint32_t*)&p0, *(uint32_t*)&p1);
}

// ---------------- HMMA bf16 GEMM (round-7 mainloop, row offset) ----------
#define GSMEM 98304
template<int EPI, bool SPLIT>
__global__ __launch_bounds__(256, 2)
void mma_gemm(const __nv_bfloat16* __restrict__ A, int K, int ldk, int N, int moff,
              const __nv_bfloat16* __restrict__ W0, const __nv_bfloat16* __restrict__ W1,
              const float* __restrict__ bias0, const float* __restrict__ bias1,
              const float* __restrict__ res, const float* __restrict__ gamma,
              float* __restrict__ outf, __nv_bfloat16* __restrict__ outb)
{
    extern __shared__ char gsm[];
    const int m0 = blockIdx.y * 128 + moff;
    const int n0 = blockIdx.x * 128;
    const int koff = blockIdx.z * K;
    const __nv_bfloat16* W = W0;
    const float* bias = bias0;
    if (SPLIT && ((m0 & (NN - 1)) >= 256)) { W = W1; bias = bias1; }

    const int tid  = threadIdx.x;
    const int lane = tid & 31;
    const int wid  = tid >> 5;
    const int wm   = wid >> 1;
    const int wn   = wid & 1;

    const uint32_t asb = smem_u32(gsm);
    const uint32_t bsb = asb + 16384u;

    const int lrow = tid >> 3;
    const int lch  = tid & 7;

    float c[2][8][4];
    #pragma unroll
    for (int i = 0; i < 2; i++)
        #pragma unroll
        for (int j = 0; j < 8; j++)
            #pragma unroll
            for (int q = 0; q < 4; q++) c[i][j][q] = 0.f;

    const int nk = K >> 6;

    auto issue = [&](int kc, int stg) {
        const __nv_bfloat16* Ap = A + koff + (size_t)m0 * ldk + kc*64;
        const __nv_bfloat16* Wp = W + koff + (size_t)n0 * ldk + kc*64;
        const uint32_t ao = asb + (uint32_t)stg * 32768u;
        const uint32_t bo = bsb + (uint32_t)stg * 32768u;
        #pragma unroll
        for (int it = 0; it < 4; ++it) {
            int row = it*32 + lrow;
            CP16(ao + SW128(row, lch), Ap + (size_t)row * ldk + lch*8);
            CP16(bo + SW128(row, lch), Wp + (size_t)row * ldk + lch*8);
        }
    };

    issue(0, 0); CPCOMMIT();
    if (nk > 1) issue(1, 1);
    CPCOMMIT();

    for (int kc = 0; kc < nk; ++kc) {
        if (kc + 2 < nk) issue(kc + 2, (kc + 2) % 3);
        CPCOMMIT();
        CPWAIT(2);
        __syncthreads();

        const uint32_t ab = asb + (uint32_t)(kc % 3) * 32768u;
        const uint32_t bb = bsb + (uint32_t)(kc % 3) * 32768u;
        #pragma unroll
        for (int kk = 0; kk < 4; ++kk) {
            uint32_t a[2][4];
            #pragma unroll
            for (int i = 0; i < 2; ++i) {
                int row = wm*32 + i*16 + (lane & 7) + ((lane >> 3) & 1) * 8;
                int ch  = 2*kk + (lane >> 4);
                LDSM4(a[i][0], a[i][1], a[i][2], a[i][3], ab + SW128(row, ch));
            }
            uint32_t b[8][2];
            #pragma unroll
            for (int jp = 0; jp < 4; ++jp) {
                int row = wn*64 + jp*16 + (lane & 7) + (lane >> 4) * 8;
                int ch  = 2*kk + ((lane >> 3) & 1);
                uint32_t t0, t1, t2, t3;
                LDSM4(t0, t1, t2, t3, bb + SW128(row, ch));
                b[jp*2][0] = t0; b[jp*2][1] = t1;
                b[jp*2+1][0] = t2; b[jp*2+1][1] = t3;
            }
            #pragma unroll
            for (int i = 0; i < 2; ++i)
                #pragma unroll
                for (int j = 0; j < 8; ++j)
                    MMA16816(c[i][j], a[i], b[j]);
        }
        __syncthreads();
    }

    float* outz = (EPI == 0) ? (outf + (size_t)blockIdx.z * M_TOK * N) : outf;
    const int g  = lane >> 2;
    const int t4 = lane & 3;
    #pragma unroll
    for (int i = 0; i < 2; ++i) {
        #pragma unroll
        for (int half = 0; half < 2; ++half) {
            const int m = m0 + wm*32 + i*16 + g + half*8;
            #pragma unroll
            for (int j = 0; j < 8; ++j) {
                const int n = n0 + wn*64 + j*8 + t4*2;
                const float v0 = c[i][j][half*2+0];
                const float v1 = c[i][j][half*2+1];
                const size_t idx = (size_t)m * N + n;
                if (EPI == 0) {
                    *(float2*)(outz + idx) = make_float2(v0, v1);
                } else if (EPI == 1) {
                    float ga = __ldg(gamma + n), gb = __ldg(gamma + n + 1);
                    float ba = __ldg(bias + n),  bbv = __ldg(bias + n + 1);
                    float ra = __ldg(res + idx), rb = __ldg(res + idx + 1);
                    *(float2*)(outf + idx) = make_float2(ra + ga*(v0 + ba), rb + gb*(v1 + bbv));
                } else if (EPI == 2) {
                    float x0 = v0 + __ldg(bias + n);
                    float x1 = v1 + __ldg(bias + n + 1);
                    float e0 = 0.5f * x0 * (1.f + erff(x0 * 0.70710678118654752440f));
                    float e1 = 0.5f * x1 * (1.f + erff(x1 * 0.70710678118654752440f));
                    *(__nv_bfloat162*)(outb + idx) = __floats2bfloat162_rn(e0, e1);
                } else { // EPI == 4
                    *(__nv_bfloat162*)(outb + idx) = __floats2bfloat162_rn(v0, v1);
                }
            }
        }
    }
}

// ---------------- fc2 split-K=2 reduce (element offset) ----------------
__global__ __launch_bounds__(256)
void fc2_reduce(const float* __restrict__ part, const float* __restrict__ bt,
                const float* __restrict__ bf, const float* __restrict__ gamma,
                float* __restrict__ out, int moff)
{
    int i = blockIdx.x * 256 + threadIdx.x;
    size_t idx = (size_t)moff * CC + (size_t)i * 4;
    int m = (int)(idx / CC);
    int n = (int)(idx % CC);
    const float* bias = ((m & (NN - 1)) >= 256) ? bf : bt;
    float4 p0 = *(const float4*)(part + idx);
    float4 p1 = *(const float4*)(part + (size_t)M_TOK*CC + idx);
    float4 o  = *(const float4*)(out + idx);
    float4 gm = *(const float4*)(gamma + n);
    float4 bs = *(const float4*)(bias + n);
    o.x += gm.x * (p0.x + p1.x + bs.x);
    o.y += gm.y * (p0.y + p1.y + bs.y);
    o.z += gm.z * (p0.z + p1.z + bs.z);
    o.w += gm.w * (p0.w + p1.w + bs.w);
    *(float4*)(out + idx) = o;
}

// ---------------- FlashAttention: register-resident P, k-split PV ----------
#define FA_Q   0u
#define FA_KV  8192u
#define FA_MRG 73728u
#define FA_LB  91136u
#define FASMEM 91648
__global__ __launch_bounds__(256, 2)
void attn_fa(const __nv_bfloat16* __restrict__ qkvb, const __nv_bfloat16* __restrict__ biasb,
             __nv_bfloat16* __restrict__ ob, int b0v)
{
    extern __shared__ char sm[];
    const uint32_t sb = smem_u32(sm);
    float* mrg  = (float*)(sm + FA_MRG);
    float* lbuf = (float*)(sm + FA_LB);

    const int q0 = blockIdx.x * 64;
    const int h  = blockIdx.y;
    const int b  = blockIdx.z + b0v;
    const int tid = threadIdx.x;
    const int lane = tid & 31;
    const int wid  = tid >> 5;
    const int wm   = wid >> 1;
    const int wn   = wid & 1;
    const int lq   = lane >> 2;
    const int lt   = lane & 3;
    const int r0   = wm*16 + lq;

    const __nv_bfloat16* brow = biasb + (size_t)h * (NN*NN);
    const float LOG2E_SCALE = 0.125f * 1.4426950408889634f;

    auto issueT = [&](int tile, int co, int bufi) {
        uint32_t base = sb + FA_KV + (uint32_t)bufi * 16384u;
        #pragma unroll
        for (int it = 0; it < 4; ++it) {
            int e = it*256 + tid;
            int row = e >> 3, ch = e & 7;
            CP16(base + SW128(row, ch),
                 qkvb + (size_t)(b*NN + tile*128 + row) * (3*CC) + co + h*DD + ch*8);
        }
    };

    #pragma unroll
    for (int it = 0; it < 2; ++it) {
        int e = it*256 + tid;
        int row = e >> 3, ch = e & 7;
        CP16(sb + FA_Q + SW128(row, ch),
             qkvb + (size_t)(b*NN + q0 + row) * (3*CC) + h*DD + ch*8);
    }
    issueT(0, CC, 0);
    CPCOMMIT();
    issueT(0, 2*CC, 1);
    CPCOMMIT();

    float o[8][4];
    #pragma unroll
    for (int j = 0; j < 8; ++j)
        #pragma unroll
        for (int q = 0; q < 4; ++q) o[j][q] = 0.f;
    float l0r = 0.f, l1r = 0.f;

    for (int t = 0; t < 4; ++t) {
        CPWAIT(1);
        __syncthreads();
        if (t < 3) { issueT(t + 1, CC, (2*t + 2) & 3); CPCOMMIT(); }
        const uint32_t kbase = sb + FA_KV + (uint32_t)((2*t) & 3) * 16384u;
        const uint32_t vbase = sb + FA_KV + (uint32_t)((2*t + 1) & 3) * 16384u;

        float s[8][4];
        #pragma unroll
        for (int j = 0; j < 8; ++j)
            #pragma unroll
            for (int q = 0; q < 4; ++q) s[j][q] = 0.f;
        #pragma unroll
        for (int kk = 0; kk < 4; ++kk) {
            uint32_t a[4];
            {
                int row = wm*16 + (lane & 7) + ((lane >> 3) & 1) * 8;
                int ch  = 2*kk + (lane >> 4);
                LDSM4(a[0], a[1], a[2], a[3], sb + FA_Q + SW128(row, ch));
            }
            uint32_t bfr[8][2];
            #pragma unroll
            for (int jp = 0; jp < 4; ++jp) {
                int row = wn*64 + jp*16 + (lane & 7) + (lane >> 4) * 8;
                int ch  = 2*kk + ((lane >> 3) & 1);
                uint32_t t0, t1, t2, t3;
                LDSM4(t0, t1, t2, t3, kbase + SW128(row, ch));
                bfr[jp*2][0] = t0; bfr[jp*2][1] = t1;
                bfr[jp*2+1][0] = t2; bfr[jp*2+1][1] = t3;
            }
            #pragma unroll
            for (int j = 0; j < 8; ++j)
                MMA16816(s[j], a, bfr[j]);
        }

        uint32_t pb[8][2];
        #pragma unroll
        for (int j = 0; j < 8; ++j) {
            int cg = t*128 + wn*64 + j*8 + lt*2;
            __nv_bfloat162 b0 = *(const __nv_bfloat162*)(brow + (size_t)(q0 + r0) * NN + cg);
            __nv_bfloat162 b1 = *(const __nv_bfloat162*)(brow + (size_t)(q0 + r0 + 8) * NN + cg);
            float p0 = ex2f(fmaf(s[j][0], LOG2E_SCALE, __bfloat162float(b0.x)));
            float p1 = ex2f(fmaf(s[j][1], LOG2E_SCALE, __bfloat162float(b0.y)));
            float p2 = ex2f(fmaf(s[j][2], LOG2E_SCALE, __bfloat162float(b1.x)));
            float p3 = ex2f(fmaf(s[j][3], LOG2E_SCALE, __bfloat162float(b1.y)));
            l0r += p0 + p1;
            l1r += p2 + p3;
            __nv_bfloat162 q01 = __floats2bfloat162_rn(p0, p1);
            __nv_bfloat162 q23 = __floats2bfloat162_rn(p2, p3);
            pb[j][0] = *(uint32_t*)&q01;
            pb[j][1] = *(uint32_t*)&q23;
        }

        if (t < 3) { CPWAIT(1); } else { CPWAIT(0); }
        #pragma unroll
        for (int kk = 0; kk < 4; ++kk) {
            uint32_t a[4] = { pb[2*kk][0], pb[2*kk][1], pb[2*kk+1][0], pb[2*kk+1][1] };
            #pragma unroll
            for (int j2 = 0; j2 < 4; ++j2) {
                int krow = wn*64 + kk*16 + (lane & 7) + ((lane >> 3) & 1) * 8;
                int ch   = j2*2 + (lane >> 4);
                uint32_t t0, t1, t2, t3;
                LDSM4T(t0, t1, t2, t3, vbase + SW128(krow, ch));
                uint32_t bv0[2] = {t0, t1}, bv1[2] = {t2, t3};
                MMA16816(o[j2*2],     a, bv0);
                MMA16816(o[j2*2 + 1], a, bv1);
            }
        }
        if (t < 3) { issueT(t + 1, 2*CC, (2*t + 3) & 3); CPCOMMIT(); }
    }

    l0r += __shfl_xor_sync(0xffffffffu, l0r, 1);
    l0r += __shfl_xor_sync(0xffffffffu, l0r, 2);
    l1r += __shfl_xor_sync(0xffffffffu, l1r, 1);
    l1r += __shfl_xor_sync(0xffffffffu, l1r, 2);

    if (wn == 1) {
        #pragma unroll
        for (int j = 0; j < 8; ++j) {
            *(float2*)(mrg + r0*68 + j*8 + lt*2)       = make_float2(o[j][0], o[j][1]);
            *(float2*)(mrg + (r0 + 8)*68 + j*8 + lt*2) = make_float2(o[j][2], o[j][3]);
        }
        if (lt == 0) { lbuf[r0] = l0r; lbuf[r0 + 8] = l1r; }
    }
    __syncthreads();
    if (wn == 0) {
        float i0 = 1.f / (l0r + lbuf[r0]);
        float i1 = 1.f / (l1r + lbuf[r0 + 8]);
        #pragma unroll
        for (int j = 0; j < 8; ++j) {
            float2 m0 = *(float2*)(mrg + r0*68 + j*8 + lt*2);
            float2 m1 = *(float2*)(mrg + (r0 + 8)*68 + j*8 + lt*2);
            int dc = j*8 + lt*2;
            __nv_bfloat16* p0 = ob + (size_t)(b*NN + q0 + r0) * CC + h*DD + dc;
            __nv_bfloat16* p1 = ob + (size_t)(b*NN + q0 + r0 + 8) * CC + h*DD + dc;
            *(__nv_bfloat162*)p0 = __floats2bfloat162_rn((o[j][0] + m0.x)*i0, (o[j][1] + m0.y)*i0);
            *(__nv_bfloat162*)p1 = __floats2bfloat162_rn((o[j][2] + m1.x)*i1, (o[j][3] + m1.y)*i1);
        }
    }
}

// ---------------- launch: dual row-pipelined streams ----------------
#define MH (M_TOK/2)   // 4096 rows per half (batches 0..7 | 8..15)
extern "C" void kernel_launch(void* const* d_in, const int* in_sizes, int n_in,
                              void* d_out, int out_size)
{
    const float* x        = (const float*)d_in[0];
    const int*   rpi      = (const int*)  d_in[2];
    const float* W_qkv    = (const float*)d_in[3];
    const float* W_proj   = (const float*)d_in[4];
    const float* b_proj   = (const float*)d_in[5];
    const float* rel_tab  = (const float*)d_in[6];
    const float* ln1_g    = (const float*)d_in[7];
    const float* ln1_b    = (const float*)d_in[8];
    const float* gamma1   = (const float*)d_in[9];
    const float* gamma2   = (const float*)d_in[10];
    const float* ln2t_g   = (const float*)d_in[11];
    const float* ln2t_b   = (const float*)d_in[12];
    const float* fc1t_W   = (const float*)d_in[13];
    const float* fc1t_b   = (const float*)d_in[14];
    const float* fc2t_W   = (const float*)d_in[15];
    const float* fc2t_b   = (const float*)d_in[16];
    const float* ln2f_g   = (const float*)d_in[17];
    const float* ln2f_b   = (const float*)d_in[18];
    const float* fc1f_W   = (const float*)d_in[19];
    const float* fc1f_b   = (const float*)d_in[20];
    const float* fc2f_W   = (const float*)d_in[21];
    const float* fc2f_b   = (const float*)d_in[22];
    float* out = (float*)d_out;

    __nv_bfloat16 *hb, *qkvb, *ob, *h2b, *hidb, *biasb, *wqkv, *wproj, *w1t, *w1f, *w2t, *w2f;
    float* part;
    cudaGetSymbolAddress((void**)&hb,    g_hb);
    cudaGetSymbolAddress((void**)&qkvb,  g_qkvb);
    cudaGetSymbolAddress((void**)&ob,    g_ob);
    cudaGetSymbolAddress((void**)&h2b,   g_h2b);
    cudaGetSymbolAddress((void**)&hidb,  g_hidb);
    cudaGetSymbolAddress((void**)&biasb, g_biasb);
    cudaGetSymbolAddress((void**)&part,  g_part);
    cudaGetSymbolAddress((void**)&wqkv,  g_wqkv);
    cudaGetSymbolAddress((void**)&wproj, g_wproj);
    cudaGetSymbolAddress((void**)&w1t,   g_w1t);
    cudaGetSymbolAddress((void**)&w1f,   g_w1f);
    cudaGetSymbolAddress((void**)&w2t,   g_w2t);
    cudaGetSymbolAddress((void**)&w2f,   g_w2f);

    cudaFuncSetAttribute(mma_gemm<0,true>,  cudaFuncAttributeMaxDynamicSharedMemorySize, GSMEM);
    cudaFuncSetAttribute(mma_gemm<1,false>, cudaFuncAttributeMaxDynamicSharedMemorySize, GSMEM);
    cudaFuncSetAttribute(mma_gemm<2,true>,  cudaFuncAttributeMaxDynamicSharedMemorySize, GSMEM);
    cudaFuncSetAttribute(mma_gemm<4,false>, cudaFuncAttributeMaxDynamicSharedMemorySize, GSMEM);
    cudaFuncSetAttribute(attn_fa,           cudaFuncAttributeMaxDynamicSharedMemorySize, FASMEM);

    static cudaStream_t s1 = [](){
        cudaStream_t s; cudaStreamCreateWithFlags(&s, cudaStreamNonBlocking); return s; }();
    static cudaStream_t s2 = [](){
        cudaStream_t s; cudaStreamCreateWithFlags(&s, cudaStreamNonBlocking); return s; }();
    static cudaEvent_t ev0, evA, evBias, evB, evLN, evDoneB;
    static bool einit = [](){
        cudaEventCreateWithFlags(&ev0,     cudaEventDisableTiming);
        cudaEventCreateWithFlags(&evA,     cudaEventDisableTiming);
        cudaEventCreateWithFlags(&evBias,  cudaEventDisableTiming);
        cudaEventCreateWithFlags(&evB,     cudaEventDisableTiming);
        cudaEventCreateWithFlags(&evLN,    cudaEventDisableTiming);
        cudaEventCreateWithFlags(&evDoneB, cudaEventDisableTiming);
        return true; }();
    (void)einit;

    // fork both side streams from origin
    cudaEventRecord(ev0, 0);
    cudaStreamWaitEvent(s1, ev0, 0);
    cudaStreamWaitEvent(s2, ev0, 0);

    // s2: bias + MLP weight converts
    bias_kernel<<<NN*NN/256, 256, 0, s2>>>(rpi, rel_tab, biasb);
    cudaEventRecord(evBias, s2);
    cvt_b<<<(4*CB0 + 255)/256, 256, 0, s2>>>(
        (const float4*)fc1t_W, (const float4*)fc1f_W,
        (const float4*)fc2t_W, (const float4*)fc2f_W,
        (__nv_bfloat162*)w1t, (__nv_bfloat162*)w1f,
        (__nv_bfloat162*)w2t, (__nv_bfloat162*)w2f);
    cudaEventRecord(evB, s2);

    // s1: attn weight convert, then pipeline B (rows MH.., batches 8..15)
    cvt_a<<<(CA1 + 255)/256, 256, 0, s1>>>(
        (const float4*)W_qkv, (const float4*)W_proj,
        (__nv_bfloat162*)wqkv, (__nv_bfloat162*)wproj);
    cudaEventRecord(evA, s1);

    // stream 0: LN1 full
    ln_kernel<<<M_TOK, 192>>>((const float4*)x, (uint2*)hb,
        (const float4*)ln1_g, (const float4*)ln1_b, nullptr, nullptr, 0, 0);
    cudaEventRecord(evLN, 0);

    // ---- pipeline A (rows 0..MH) on stream 0 ----
    cudaStreamWaitEvent(0, evA, 0);
    mma_gemm<4,false><<<dim3(3*CC/128, MH/128), 256, GSMEM>>>(
        hb, CC, CC, 3*CC, 0, wqkv, nullptr, nullptr, nullptr, nullptr, nullptr, nullptr, qkvb);
    cudaStreamWaitEvent(0, evBias, 0);
    attn_fa<<<dim3(NN/64, HH, BB/2), 256, FASMEM>>>(qkvb, biasb, ob, 0);
    mma_gemm<1,false><<<dim3(CC/128, MH/128), 256, GSMEM>>>(
        ob, CC, CC, CC, 0, wproj, nullptr, b_proj, nullptr, x, gamma1, out, nullptr);
    ln_kernel<<<MH, 192>>>((const float4*)out, (uint2*)h2b,
        (const float4*)ln2t_g, (const float4*)ln2t_b,
        (const float4*)ln2f_g, (const float4*)ln2f_b, 1, 0);
    cudaStreamWaitEvent(0, evB, 0);
    mma_gemm<2,true><<<dim3(HID/128, MH/128), 256, GSMEM>>>(
        h2b, CC, CC, HID, 0, w1t, w1f, fc1t_b, fc1f_b, nullptr, nullptr, nullptr, hidb);
    mma_gemm<0,true><<<dim3(CC/128, MH/128, 2), 256, GSMEM>>>(
        hidb, HID/2, HID, CC, 0, w2t, w2f, nullptr, nullptr, nullptr, nullptr, part, nullptr);
    fc2_reduce<<<MH*CC/1024, 256>>>(part, fc2t_b, fc2f_b, gamma2, out, 0);

    // ---- pipeline B (rows MH.., batches 8..15) on s1 ----
    cudaStreamWaitEvent(s1, evLN, 0);
    mma_gemm<4,false><<<dim3(3*CC/128, MH/128), 256, GSMEM, s1>>>(
        hb, CC, CC, 3*CC, MH, wqkv, nullptr, nullptr, nullptr, nullptr, nullptr, nullptr, qkvb);
    cudaStreamWaitEvent(s1, evBias, 0);
    attn_fa<<<dim3(NN/64, HH, BB/2), 256, FASMEM, s1>>>(qkvb, biasb, ob, BB/2);
    mma_gemm<1,false><<<dim3(CC/128, MH/128), 256, GSMEM, s1>>>(
        ob, CC, CC, CC, MH, wproj, nullptr, b_proj, nullptr, x, gamma1, out, nullptr);
    ln_kernel<<<MH, 192, 0, s1>>>((const float4*)out, (uint2*)h2b,
        (const float4*)ln2t_g, (const float4*)ln2t_b,
        (const float4*)ln2f_g, (const float4*)ln2f_b, 1, MH);
    cudaStreamWaitEvent(s1, evB, 0);
    mma_gemm<2,true><<<dim3(HID/128, MH/128), 256, GSMEM, s1>>>(
        h2b, CC, CC, HID, MH, w1t, w1f, fc1t_b, fc1f_b, nullptr, nullptr, nullptr, hidb);
    mma_gemm<0,true><<<dim3(CC/128, MH/128, 2), 256, GSMEM, s1>>>(
        hidb, HID/2, HID, CC, MH, w2t, w2f, nullptr, nullptr, nullptr, nullptr, part, nullptr);
    fc2_reduce<<<MH*CC/1024, 256, 0, s1>>>(part, fc2t_b, fc2f_b, gamma2, out, MH);
    cudaEventRecord(evDoneB, s1);

    // join
    cudaStreamWaitEvent(0, evDoneB, 0);
}